// round 8
// baseline (speedup 1.0000x reference)
#include <cuda_runtime.h>
#include <cuda_bf16.h>
#include <cstdint>

#define HASH_SIZE 256
#define OFFSET_SIZE 64

// L2 range policy: first 100MB of hash table evict_last (fits in 126MB L2,
// persists across graph replays), rest evict_first. Kept from R6 (profiled
// launch showed +3% HBM efficiency, no downside).
#define PRIMARY_BYTES (100u * 1024u * 1024u)
#define TOTAL_BYTES   (512u * 1024u * 1024u)

__device__ __forceinline__ uint64_t make_range_policy(const void* base) {
    uint64_t pol;
    asm("createpolicy.range.global.L2::evict_last.L2::evict_first.b64 %0, [%1], %2, %3;"
        : "=l"(pol)
        : "l"(base), "r"(PRIMARY_BYTES), "r"(TOTAL_BYTES));
    return pol;
}

__device__ __forceinline__ void ldg256_hint(const void* p, uint64_t pol, uint32_t* r) {
    asm("ld.global.cg.L2::cache_hint.v8.b32 {%0,%1,%2,%3,%4,%5,%6,%7}, [%8], %9;"
        : "=r"(r[0]), "=r"(r[1]), "=r"(r[2]), "=r"(r[3]),
          "=r"(r[4]), "=r"(r[5]), "=r"(r[6]), "=r"(r[7])
        : "l"(p), "l"(pol));
}

__device__ __forceinline__ void stg256_cs(void* p, const uint32_t* r) {
    asm volatile("st.global.cs.v8.b32 [%0], {%1,%2,%3,%4,%5,%6,%7,%8};"
                 :: "l"(p),
                    "r"(r[0]), "r"(r[1]), "r"(r[2]), "r"(r[3]),
                    "r"(r[4]), "r"(r[5]), "r"(r[6]), "r"(r[7])
                 : "memory");
}

__global__ __launch_bounds__(256)
void psh_kernel(const int* __restrict__ coords,
                const float* __restrict__ hash_table,
                const int* __restrict__ offset_table,
                const float* __restrict__ m0,
                const float* __restrict__ m1,
                float* __restrict__ out,
                int n, int half)
{
    int i = blockIdx.x * blockDim.x + threadIdx.x;
    if (i >= half) return;

    uint64_t pol = make_range_policy(hash_table);

    int qa = i;
    int qb = i + half;
    bool has_b = (qb < n);

    // --- stage 1: both coords loads in flight (coalesced, streaming) ---
    int a0 = __ldcs(&coords[3 * qa + 0]);
    int a1 = __ldcs(&coords[3 * qa + 1]);
    int a2 = __ldcs(&coords[3 * qa + 2]);
    int b0 = 0, b1 = 0, b2 = 0;
    if (has_b) {
        b0 = __ldcs(&coords[3 * qb + 0]);
        b1 = __ldcs(&coords[3 * qb + 1]);
        b2 = __ldcs(&coords[3 * qb + 2]);
    }

    float m1x = __ldg(&m1[0]), m1y = __ldg(&m1[1]), m1z = __ldg(&m1[2]);
    float m0x = __ldg(&m0[0]), m0y = __ldg(&m0[1]), m0z = __ldg(&m0[2]);

    // --- stage 2: both offset-table gathers in flight (L2-resident) ---
    int oa = (((((int)((float)a0 * m1x)) & (OFFSET_SIZE - 1)) * OFFSET_SIZE +
               (((int)((float)a1 * m1y)) & (OFFSET_SIZE - 1))) * OFFSET_SIZE +
               (((int)((float)a2 * m1z)) & (OFFSET_SIZE - 1))) * 3;
    int ob = (((((int)((float)b0 * m1x)) & (OFFSET_SIZE - 1)) * OFFSET_SIZE +
               (((int)((float)b1 * m1y)) & (OFFSET_SIZE - 1))) * OFFSET_SIZE +
               (((int)((float)b2 * m1z)) & (OFFSET_SIZE - 1))) * 3;

    int fa0 = __ldg(&offset_table[oa + 0]);
    int fa1 = __ldg(&offset_table[oa + 1]);
    int fa2 = __ldg(&offset_table[oa + 2]);
    int fb0 = 0, fb1 = 0, fb2 = 0;
    if (has_b) {
        fb0 = __ldg(&offset_table[ob + 0]);
        fb1 = __ldg(&offset_table[ob + 1]);
        fb2 = __ldg(&offset_table[ob + 2]);
    }

    // --- stage 3: both DRAM hash gathers in flight (the expensive ones) ---
    int ha0 = (((int)((float)a0 * m0x)) + fa0) & (HASH_SIZE - 1);
    int ha1 = (((int)((float)a1 * m0y)) + fa1) & (HASH_SIZE - 1);
    int ha2 = (((int)((float)a2 * m0z)) + fa2) & (HASH_SIZE - 1);
    long long hia = (long long)((ha0 * HASH_SIZE + ha1) * HASH_SIZE + ha2);

    int hb0 = (((int)((float)b0 * m0x)) + fb0) & (HASH_SIZE - 1);
    int hb1 = (((int)((float)b1 * m0y)) + fb1) & (HASH_SIZE - 1);
    int hb2 = (((int)((float)b2 * m0z)) + fb2) & (HASH_SIZE - 1);
    long long hib = (long long)((hb0 * HASH_SIZE + hb1) * HASH_SIZE + hb2);

    uint32_t ra[8], rb[8];
    ldg256_hint(hash_table + hia * 8, pol, ra);
    if (has_b) ldg256_hint(hash_table + hib * 8, pol, rb);

    // --- stage 4: stores ---
    stg256_cs(out + (long long)qa * 8, ra);
    if (has_b) stg256_cs(out + (long long)qb * 8, rb);
}

extern "C" void kernel_launch(void* const* d_in, const int* in_sizes, int n_in,
                              void* d_out, int out_size)
{
    const int*   coords       = (const int*)d_in[0];
    const float* hash_table   = (const float*)d_in[1];
    const int*   offset_table = (const int*)d_in[2];
    const float* m0           = (const float*)d_in[3];
    const float* m1           = (const float*)d_in[4];
    float*       out          = (float*)d_out;

    int n = in_sizes[0] / 3;
    int half = (n + 1) / 2;
    int threads = 256;
    int blocks = (half + threads - 1) / threads;
    psh_kernel<<<blocks, threads>>>(coords, hash_table, offset_table, m0, m1, out, n, half);
}